// round 10
// baseline (speedup 1.0000x reference)
#include <cuda_runtime.h>
#include <cuda_bf16.h>
#include <cuda_fp16.h>
#include <cstdint>

#define H        128
#define NROWS    200000
#define NTILES   ((NROWS + 127) / 128)   // 1563
#define M_NODES  1000
#define J_NODES  5000
#define SBLOCKS  296                     // 2 blocks/SM
#define NWTOT    SBLOCKS

// staged row stride: 272 = 16*17 -> 16B-aligned ldmatrix rows, bank shift 4.
#define HSB       272

// score kernel smem: two h buffers + two part buffers + c copy
#define BUFSZ     (128 * HSB)            // 34816
#define PART_OFF  (2 * BUFSZ)            // 69632 (2 x 4096)
#define CS_OFF    (PART_OFF + 8192)      // 77824
#define SMEM_SZ   (CS_OFF + 512)         // 78336

// precompute kernel smem (hi + lo bf16, 64 rows)
#define P_LO_OFF  (64 * HSB)             // 17408
#define P_SMEM    (2 * 64 * HSB)         // 34816
#define NT_M      16                     // ceil(1000/64)
#define NT_J      79                     // ceil(5000/64)

// ---------------- device scratch ----------------
__device__ __align__(16) float g_c[H];
__device__ __align__(16) float g_A[M_NODES * H];
__device__ __align__(16) float g_B[J_NODES * H];
__device__ float g_wmax[NWTOT];
__device__ int   g_warg[NWTOT];
__device__ float g_wZ[NWTOT];
__device__ float g_wS1[NWTOT];

// ---------------- PTX helpers (generic ISA only) ----------------
__device__ __forceinline__ uint32_t smem_u32(const void* p) {
    uint32_t a;
    asm("{ .reg .u64 t; cvta.to.shared.u64 t, %1; cvt.u32.u64 %0, t; }" : "=r"(a) : "l"(p));
    return a;
}
__device__ __forceinline__ void ldsm_x4(uint32_t* r, uint32_t addr) {
    asm volatile("ldmatrix.sync.aligned.m8n8.x4.shared.b16 {%0,%1,%2,%3}, [%4];"
        : "=r"(r[0]), "=r"(r[1]), "=r"(r[2]), "=r"(r[3]) : "r"(addr));
}
__device__ __forceinline__ void mma_bf16(float* d, const uint32_t* a, const uint32_t* b) {
    asm volatile("mma.sync.aligned.m16n8k16.row.col.f32.bf16.bf16.f32 "
        "{%0,%1,%2,%3}, {%4,%5,%6,%7}, {%8,%9}, {%0,%1,%2,%3};"
        : "+f"(d[0]), "+f"(d[1]), "+f"(d[2]), "+f"(d[3])
        : "r"(a[0]), "r"(a[1]), "r"(a[2]), "r"(a[3]), "r"(b[0]), "r"(b[1]));
}
__device__ __forceinline__ void mma_f16(float* d, const uint32_t* a, const uint32_t* b) {
    asm volatile("mma.sync.aligned.m16n8k16.row.col.f32.f16.f16.f32 "
        "{%0,%1,%2,%3}, {%4,%5,%6,%7}, {%8,%9}, {%0,%1,%2,%3};"
        : "+f"(d[0]), "+f"(d[1]), "+f"(d[2]), "+f"(d[3])
        : "r"(a[0]), "r"(a[1]), "r"(a[2]), "r"(a[3]), "r"(b[0]), "r"(b[1]));
}
__device__ __forceinline__ uint32_t pack_bf2(float lo, float hi) {
    __nv_bfloat162 t;
    t.x = __float2bfloat16_rn(lo);
    t.y = __float2bfloat16_rn(hi);
    return *(uint32_t*)&t;
}
__device__ __forceinline__ uint32_t pack_h2(float lo, float hi) {
    __half2 t = __floats2half2_rn(lo, hi);
    return *(uint32_t*)&t;
}

// ---------------- K1: precompute (bf16 3-product HMMA, column-split) -------
// Block: 64 rows x 64 outcols. b&1 selects column half. Last block: g_c fp32.
__global__ void __launch_bounds__(256, 2) precompute_kernel(
        const float* __restrict__ xg, const float* __restrict__ xm,
        const float* __restrict__ xj, const float* __restrict__ W0,
        const float* __restrict__ b0) {
    extern __shared__ char smem[];
    __shared__ float x2[2 * H];
    int b = blockIdx.x, tid = threadIdx.x;

    if (b == 2 * (NT_M + NT_J)) {
        x2[tid] = xg[tid];
        __syncthreads();
        if (tid < H) {
            float acc = b0[tid];
            const float* w = W0 + tid;
            #pragma unroll 8
            for (int i = 0; i < 2 * H; i++) acc += x2[i] * w[i * H];
            g_c[tid] = acc;
        }
        return;
    }

    const float* src; float* dst; int r0, cnt, woff, cbase;
    if (b < 2 * NT_M) {
        src = xm; dst = g_A; cnt = M_NODES; woff = 2 * H;
        r0 = (b >> 1) * 64; cbase = (b & 1) * 64;
    } else {
        int bb = b - 2 * NT_M;
        src = xj; dst = g_B; cnt = J_NODES; woff = 3 * H;
        r0 = (bb >> 1) * 64; cbase = (bb & 1) * 64;
    }

    uint32_t sbase = smem_u32(smem);
    int lane = tid & 31, wid = tid >> 5;
    int g = lane >> 2, tig = lane & 3;

    // W0 fragments hi/lo: this warp's 8 outcols (16 LDG/thread)
    uint32_t Bh[8][2], Bl[8][2];
    {
        int n = cbase + wid * 8 + g;
        #pragma unroll
        for (int kk = 0; kk < 8; kk++)
            #pragma unroll
            for (int e = 0; e < 2; e++) {
                int k0 = kk * 16 + 2 * tig + e * 8;
                float wa = W0[(woff + k0) * H + n];
                float wb = W0[(woff + k0 + 1) * H + n];
                float ha = __bfloat162float(__float2bfloat16_rn(wa));
                float hb = __bfloat162float(__float2bfloat16_rn(wb));
                Bh[kk][e] = pack_bf2(ha, hb);
                Bl[kk][e] = pack_bf2(wa - ha, wb - hb);
            }
    }

    // stage 64 x-rows, all 256 threads (4 threads/row)
    {
        int row = tid >> 2, q = tid & 3;
        char* rh = smem + row * HSB;
        char* rl = rh + P_LO_OFF;
        int r = r0 + row;
        if (r < cnt) {
            const float4* xr = (const float4*)(src + r * H);
            #pragma unroll
            for (int c = q * 8; c < q * 8 + 8; c++) {
                float4 x = xr[c];
                float ix = __bfloat162float(__float2bfloat16_rn(x.x));
                float iy = __bfloat162float(__float2bfloat16_rn(x.y));
                float iz = __bfloat162float(__float2bfloat16_rn(x.z));
                float iw = __bfloat162float(__float2bfloat16_rn(x.w));
                uint2 hv, lv;
                hv.x = pack_bf2(ix, iy);
                hv.y = pack_bf2(iz, iw);
                lv.x = pack_bf2(x.x - ix, x.y - iy);
                lv.y = pack_bf2(x.z - iz, x.w - iw);
                *(uint2*)(rh + 8 * c) = hv;
                *(uint2*)(rl + 8 * c) = lv;
            }
        } else {
            uint2 zz = make_uint2(0u, 0u);
            #pragma unroll
            for (int c = q * 8; c < q * 8 + 8; c++) {
                *(uint2*)(rh + 8 * c) = zz;
                *(uint2*)(rl + 8 * c) = zz;
            }
        }
    }
    __syncthreads();

    uint32_t laneoff = (uint32_t)(((lane & 7) + ((lane >> 3) & 1) * 8) * HSB
                                  + ((lane >> 4) & 1) * 16);

    #pragma unroll 1
    for (int mt = 0; mt < 4; mt++) {
        float d0[4] = {0.f, 0.f, 0.f, 0.f};
        uint32_t ahi = sbase + (uint32_t)(mt * 16 * HSB) + laneoff;
        uint32_t alo = ahi + P_LO_OFF;
        #pragma unroll
        for (int kk = 0; kk < 8; kk++) {
            uint32_t ah[4], al[4];
            ldsm_x4(ah, ahi + kk * 32);
            ldsm_x4(al, alo + kk * 32);
            mma_bf16(d0, ah, Bh[kk]);
            mma_bf16(d0, ah, Bl[kk]);
            mma_bf16(d0, al, Bh[kk]);
        }
        int row0 = r0 + mt * 16 + g;
        int row1 = row0 + 8;
        int c0 = cbase + wid * 8 + 2 * tig;
        if (row0 < cnt)
            *(float2*)&dst[row0 * H + c0] = make_float2(d0[0], d0[1]);
        if (row1 < cnt)
            *(float2*)&dst[row1 * H + c0] = make_float2(d0[2], d0[3]);
    }
}

// ---------------- K2: fp16 HMMA score kernel, single-sync pipeline ---------
__global__ void __launch_bounds__(256, 2) score_kernel(
        const int*   __restrict__ m_ids, const int* __restrict__ job_idx,
        const float* __restrict__ W1,    const float* __restrict__ b1,
        const float* __restrict__ W2,    const float* __restrict__ b2) {
    extern __shared__ char smem[];
    uint32_t sbase = smem_u32(smem);
    float* cs = (float*)(smem + CS_OFF);

    int tid  = threadIdx.x;
    int lane = tid & 31;
    int wid  = tid >> 5;
    int g    = lane >> 2;
    int tig  = lane & 3;

    // W1 fragments (fp16), once
    uint32_t Fh[8][2][2];
    {
        int n = wid * 16 + g;
        #pragma unroll
        for (int kk = 0; kk < 8; kk++)
            #pragma unroll
            for (int lnt = 0; lnt < 2; lnt++)
                #pragma unroll
                for (int e = 0; e < 2; e++) {
                    int k0 = kk * 16 + 2 * tig + e * 8;
                    Fh[kk][lnt][e] = pack_h2(W1[k0 * H + n + lnt * 8],
                                             W1[(k0 + 1) * H + n + lnt * 8]);
                }
    }
    float b1c[2][2], w2c[2][2];
    #pragma unroll
    for (int lnt = 0; lnt < 2; lnt++)
        #pragma unroll
        for (int e = 0; e < 2; e++) {
            int col = wid * 16 + lnt * 8 + 2 * tig + e;
            b1c[lnt][e] = b1[col];
            w2c[lnt][e] = W2[col];
        }
    float b2v = b2[0];
    if (tid < H) cs[tid] = g_c[tid];
    __syncthreads();

    const float4* A4 = (const float4*)g_A;
    const float4* B4 = (const float4*)g_B;
    const float4* C4 = (const float4*)cs;

    uint32_t laneoff = (uint32_t)(((lane & 7) + ((lane >> 3) & 1) * 8) * HSB
                                  + ((lane >> 4) & 1) * 16);

    // stage: all 256 threads, 2 threads per row (col halves)
    #define STAGE(BOFF, TILE)                                                \
    do {                                                                     \
        int row = tid >> 1, ch = tid & 1;                                    \
        char* rh = smem + (BOFF) + row * HSB;                                \
        int grow = (TILE) * 128 + row;                                       \
        if (grow < NROWS) {                                                  \
            int m = m_ids[grow], j = job_idx[grow];                          \
            const float4* Am = A4 + m * 32;                                  \
            const float4* Bj = B4 + j * 32;                                  \
            _Pragma("unroll")                                                \
            for (int c = ch * 16; c < ch * 16 + 16; c++) {                   \
                float4 a = Am[c], bb = Bj[c], cc = C4[c];                    \
                float hx = fmaxf(cc.x + a.x + bb.x, 0.f);                    \
                float hy = fmaxf(cc.y + a.y + bb.y, 0.f);                    \
                float hz = fmaxf(cc.z + a.z + bb.z, 0.f);                    \
                float hw = fmaxf(cc.w + a.w + bb.w, 0.f);                    \
                uint2 hv;                                                    \
                hv.x = pack_h2(hx, hy);                                      \
                hv.y = pack_h2(hz, hw);                                      \
                *(uint2*)(rh + 8 * c) = hv;                                  \
            }                                                                \
        } else {                                                             \
            uint2 zz = make_uint2(0u, 0u);                                   \
            _Pragma("unroll")                                                \
            for (int c = ch * 16; c < ch * 16 + 16; c++)                     \
                *(uint2*)(rh + 8 * c) = zz;                                  \
        }                                                                    \
    } while (0)

    float mx = -3.402823466e38f, Z = 0.f, S1 = 0.f;
    int   arg = 0x7fffffff;

    int tile = blockIdx.x;
    int cur = 0, par = 0;
    if (tile < NTILES) { STAGE(0, tile); }
    __syncthreads();

    for (; tile < NTILES; tile += SBLOCKS) {
        float* pp = (float*)(smem + PART_OFF) + par * 1024;
        uint32_t boff = (uint32_t)cur * BUFSZ;

        // mma over current buffer, partials into pp
        #pragma unroll 1
        for (int mt = 0; mt < 8; mt++) {
            float d0[4] = {0.f, 0.f, 0.f, 0.f};
            float d1[4] = {0.f, 0.f, 0.f, 0.f};
            uint32_t ahi = sbase + boff + (uint32_t)(mt * 16 * HSB) + laneoff;
            #pragma unroll
            for (int kk = 0; kk < 8; kk++) {
                uint32_t ah[4];
                ldsm_x4(ah, ahi + kk * 32);
                mma_f16(d0, ah, Fh[kk][0]);
                mma_f16(d1, ah, Fh[kk][1]);
            }
            float sg = fmaxf(d0[0] + b1c[0][0], 0.f) * w2c[0][0]
                     + fmaxf(d0[1] + b1c[0][1], 0.f) * w2c[0][1]
                     + fmaxf(d1[0] + b1c[1][0], 0.f) * w2c[1][0]
                     + fmaxf(d1[1] + b1c[1][1], 0.f) * w2c[1][1];
            float sh = fmaxf(d0[2] + b1c[0][0], 0.f) * w2c[0][0]
                     + fmaxf(d0[3] + b1c[0][1], 0.f) * w2c[0][1]
                     + fmaxf(d1[2] + b1c[1][0], 0.f) * w2c[1][0]
                     + fmaxf(d1[3] + b1c[1][1], 0.f) * w2c[1][1];
            sg += __shfl_xor_sync(0xffffffffu, sg, 1);
            sg += __shfl_xor_sync(0xffffffffu, sg, 2);
            sh += __shfl_xor_sync(0xffffffffu, sh, 1);
            sh += __shfl_xor_sync(0xffffffffu, sh, 2);
            if (tig == 0) {
                pp[wid * 128 + mt * 16 + g]     = sg;
                pp[wid * 128 + mt * 16 + 8 + g] = sh;
            }
        }

        // stage next tile into the other buffer (overlaps other warps' mma)
        int ntile = tile + SBLOCKS;
        if (ntile < NTILES) { STAGE((cur ^ 1) * BUFSZ, ntile); }

        __syncthreads();   // single sync per tile

        // per-row score + online softmax (threads 0..127)
        if (tid < 128) {
            int grow = tile * 128 + tid;
            if (grow < NROWS) {
                float s = b2v;
                #pragma unroll
                for (int w = 0; w < 8; w++) s += pp[w * 128 + tid];
                if (s > mx) {
                    float dd = fmaxf(mx - s, -87.f);
                    float e = expf(dd);
                    S1 = e * (S1 + dd * Z);
                    Z  = e * Z + 1.f;
                    mx = s;
                    arg = grow;
                } else {
                    float t = fmaxf(s - mx, -87.f);
                    float e = expf(t);
                    Z  += e;
                    S1 += t * e;
                }
            }
        }
        cur ^= 1; par ^= 1;
    }
    #undef STAGE
    __syncthreads();

    // block merge of per-thread softmax states (reuse part region)
    float* smx = (float*)(smem + PART_OFF);
    float* sZ  = smx + 256;
    float* sS1 = smx + 512;
    int*   sarg = (int*)(smx + 768);
    smx[tid] = mx; sZ[tid] = Z; sS1[tid] = S1; sarg[tid] = arg;
    __syncthreads();
    for (int s = 128; s; s >>= 1) {
        if (tid < s) {
            float qm = smx[tid + s], qZ = sZ[tid + s], qS = sS1[tid + s];
            int   qa = sarg[tid + s];
            if (qm > smx[tid] || (qm == smx[tid] && qa < sarg[tid])) {
                float d = fmaxf(smx[tid] - qm, -87.f);
                float e = expf(d);
                float Zo = sZ[tid], S1o = sS1[tid];
                sZ[tid]  = qZ + e * Zo;
                sS1[tid] = qS + e * (S1o + d * Zo);
                smx[tid] = qm; sarg[tid] = qa;
            } else {
                float d = fmaxf(qm - smx[tid], -87.f);
                float e = expf(d);
                sZ[tid]  += e * qZ;
                sS1[tid] += e * (qS + d * qZ);
            }
        }
        __syncthreads();
    }
    if (tid == 0) {
        g_wmax[blockIdx.x] = smx[0];
        g_warg[blockIdx.x] = sarg[0];
        g_wZ[blockIdx.x]   = sZ[0];
        g_wS1[blockIdx.x]  = sS1[0];
    }
}

// ---------------- K3: merge 296 block partials ----------------
__global__ void __launch_bounds__(512) finalize_kernel(float* __restrict__ out) {
    __shared__ float smx[512], sZ[512], sS1[512];
    __shared__ int   sarg[512];
    int tid = threadIdx.x;

    float mx = -3.402823466e38f, Z = 0.f, S1 = 0.f;
    int   arg = 0x7fffffff;
    if (tid < NWTOT) { mx = g_wmax[tid]; Z = g_wZ[tid]; S1 = g_wS1[tid]; arg = g_warg[tid]; }
    smx[tid] = mx; sarg[tid] = arg; sZ[tid] = Z; sS1[tid] = S1;
    __syncthreads();

    for (int s = 256; s; s >>= 1) {
        if (tid < s) {
            float qm = smx[tid + s], qZ = sZ[tid + s], qS = sS1[tid + s];
            int   qa = sarg[tid + s];
            if (qm > smx[tid] || (qm == smx[tid] && qa < sarg[tid])) {
                float d = fmaxf(smx[tid] - qm, -87.f);
                float e = expf(d);
                float Zo = sZ[tid], S1o = sS1[tid];
                sZ[tid]  = qZ + e * Zo;
                sS1[tid] = qS + e * (S1o + d * Zo);
                smx[tid] = qm; sarg[tid] = qa;
            } else {
                float d = fmaxf(qm - smx[tid], -87.f);
                float e = expf(d);
                sZ[tid]  += e * qZ;
                sS1[tid] += e * (qS + d * qZ);
            }
        }
        __syncthreads();
    }

    if (tid == 0) {
        float Zf = sZ[0], S1f = sS1[0];
        float logZ = logf(Zf);
        out[0] = (float)sarg[0];
        out[1] = 1.0f / Zf;          // p[idx]
        out[2] = -logZ;              // logp[idx]
        out[3] = logZ - S1f / Zf;    // entropy
    }
}

// ---------------- launch ----------------
extern "C" void kernel_launch(void* const* d_in, const int* in_sizes, int n_in,
                              void* d_out, int out_size) {
    const float* x_graph = (const float*)d_in[0];
    const float* x_m     = (const float*)d_in[1];
    const float* x_job   = (const float*)d_in[2];
    const int*   m_ids   = (const int*)  d_in[3];
    const int*   job_idx = (const int*)  d_in[4];
    const float* W0      = (const float*)d_in[5];
    const float* b0      = (const float*)d_in[6];
    const float* W1      = (const float*)d_in[7];
    const float* b1      = (const float*)d_in[8];
    const float* W2      = (const float*)d_in[9];
    const float* b2      = (const float*)d_in[10];
    float* out = (float*)d_out;

    cudaFuncSetAttribute(precompute_kernel,
                         cudaFuncAttributeMaxDynamicSharedMemorySize, P_SMEM);
    cudaFuncSetAttribute(score_kernel,
                         cudaFuncAttributeMaxDynamicSharedMemorySize, SMEM_SZ);

    precompute_kernel<<<2 * (NT_M + NT_J) + 1, 256, P_SMEM>>>(x_graph, x_m, x_job, W0, b0);
    score_kernel<<<SBLOCKS, 256, SMEM_SZ>>>(m_ids, job_idx, W1, b1, W2, b2);
    finalize_kernel<<<1, 512>>>(out);
}

// round 11
// speedup vs baseline: 1.4004x; 1.4004x over previous
#include <cuda_runtime.h>
#include <cuda_bf16.h>
#include <cuda_fp16.h>
#include <cstdint>

#define H        128
#define NROWS    200000
#define NTILES   ((NROWS + 127) / 128)   // 1563
#define M_NODES  1000
#define J_NODES  5000
#define SBLOCKS  296                     // 2 blocks/SM, exactly resident
#define NWTOT    SBLOCKS

// staged row stride: 272B (row data 256B fp16 + 16 pad) -> 16B-aligned
// ldmatrix rows, per-row bank shift 68 mod 32 = 4 -> conflict-free.
#define HSB       272
#define PART_OFF  (128 * HSB)            // 34816
#define CS_OFF    (PART_OFF + 4096)      // 38912
#define SMEM_SZ   (CS_OFF + 512)         // 39424  (2 blocks/SM fits easily)

// precompute prologue tiling (32 rows per block)
#define NT_PM     32                     // ceil(1000/32)
#define NT_PJ     157                    // ceil(5000/32)
#define NT_TOT    (NT_PM + NT_PJ)        // 189

// ---------------- device scratch ----------------
__device__ __align__(16) __half g_c[H];
__device__ __align__(16) __half g_A[M_NODES * H];
__device__ __align__(16) __half g_B[J_NODES * H];
__device__ int   g_bar;
__device__ float g_wmax[NWTOT];
__device__ int   g_warg[NWTOT];
__device__ float g_wZ[NWTOT];
__device__ float g_wS1[NWTOT];

// ---------------- PTX helpers (generic ISA only) ----------------
__device__ __forceinline__ uint32_t smem_u32(const void* p) {
    uint32_t a;
    asm("{ .reg .u64 t; cvta.to.shared.u64 t, %1; cvt.u32.u64 %0, t; }" : "=r"(a) : "l"(p));
    return a;
}
__device__ __forceinline__ void ldsm_x4(uint32_t* r, uint32_t addr) {
    asm volatile("ldmatrix.sync.aligned.m8n8.x4.shared.b16 {%0,%1,%2,%3}, [%4];"
        : "=r"(r[0]), "=r"(r[1]), "=r"(r[2]), "=r"(r[3]) : "r"(addr));
}
__device__ __forceinline__ void mma_f16(float* d, const uint32_t* a, const uint32_t* b) {
    asm volatile("mma.sync.aligned.m16n8k16.row.col.f32.f16.f16.f32 "
        "{%0,%1,%2,%3}, {%4,%5,%6,%7}, {%8,%9}, {%0,%1,%2,%3};"
        : "+f"(d[0]), "+f"(d[1]), "+f"(d[2]), "+f"(d[3])
        : "r"(a[0]), "r"(a[1]), "r"(a[2]), "r"(a[3]), "r"(b[0]), "r"(b[1]));
}
__device__ __forceinline__ uint32_t pack_h2(float lo, float hi) {
    __half2 t = __floats2half2_rn(lo, hi);
    return *(uint32_t*)&t;
}
__device__ __forceinline__ uint32_t h2_addmax0(uint32_t a, uint32_t b, uint32_t c) {
    __half2 r = __hadd2(__hadd2(*(__half2*)&a, *(__half2*)&b), *(__half2*)&c);
    __half2 z = __float2half2_rn(0.f);
    r = __hmax2(r, z);
    return *(uint32_t*)&r;
}

// ---------------- K0: reset barrier (graph-replay safe) ----------------
__global__ void zero_bar_kernel() { g_bar = 0; }

// ---------------- K1: fused precompute + score (persistent grid) ----------
__global__ void __launch_bounds__(256, 2) score_kernel(
        const float* __restrict__ xg,    const float* __restrict__ xm,
        const float* __restrict__ xj,    const float* __restrict__ W0,
        const float* __restrict__ b0,
        const int*   __restrict__ m_ids, const int* __restrict__ job_idx,
        const float* __restrict__ W1,    const float* __restrict__ b1,
        const float* __restrict__ W2,    const float* __restrict__ b2) {
    extern __shared__ char smem[];
    uint32_t sbase = smem_u32(smem);
    float* part = (float*)(smem + PART_OFF);
    __half* cs  = (__half*)(smem + CS_OFF);

    int tid  = threadIdx.x;
    int lane = tid & 31;
    int wid  = tid >> 5;
    int g    = lane >> 2;
    int tig  = lane & 3;
    int b    = blockIdx.x;

    uint32_t laneoff = (uint32_t)(((lane & 7) + ((lane >> 3) & 1) * 8) * HSB
                                  + ((lane >> 4) & 1) * 16);

    // ================= PHASE 1: distributed precompute =================
    if (b < NT_TOT) {
        const float* src; __half* dst; int r0, cnt, woff;
        if (b < NT_PM) { src = xm; dst = g_A; r0 = b * 32;           cnt = M_NODES; woff = 2 * H; }
        else           { src = xj; dst = g_B; r0 = (b - NT_PM) * 32; cnt = J_NODES; woff = 3 * H; }

        // W0 fragments fp16: warp owns 16 outcols
        uint32_t Fp[8][2][2];
        {
            int n = wid * 16 + g;
            #pragma unroll
            for (int kk = 0; kk < 8; kk++)
                #pragma unroll
                for (int lnt = 0; lnt < 2; lnt++)
                    #pragma unroll
                    for (int e = 0; e < 2; e++) {
                        int k0 = kk * 16 + 2 * tig + e * 8;
                        Fp[kk][lnt][e] = pack_h2(W0[(woff + k0) * H + n + lnt * 8],
                                                 W0[(woff + k0 + 1) * H + n + lnt * 8]);
                    }
        }

        // stage 32 x-rows as fp16 (8 threads/row, 16 halves each)
        {
            int row = tid >> 3, p = tid & 7;
            char* rh = smem + row * HSB;
            int r = r0 + row;
            if (r < cnt) {
                const float4* xr = (const float4*)(src + r * H) + p * 4;
                float4 v0 = xr[0], v1 = xr[1], v2 = xr[2], v3 = xr[3];
                uint4 o0, o1;
                o0.x = pack_h2(v0.x, v0.y); o0.y = pack_h2(v0.z, v0.w);
                o0.z = pack_h2(v1.x, v1.y); o0.w = pack_h2(v1.z, v1.w);
                o1.x = pack_h2(v2.x, v2.y); o1.y = pack_h2(v2.z, v2.w);
                o1.z = pack_h2(v3.x, v3.y); o1.w = pack_h2(v3.z, v3.w);
                *(uint4*)(rh + p * 32)      = o0;
                *(uint4*)(rh + p * 32 + 16) = o1;
            } else {
                uint4 zz = make_uint4(0u, 0u, 0u, 0u);
                *(uint4*)(rh + p * 32)      = zz;
                *(uint4*)(rh + p * 32 + 16) = zz;
            }
        }
        __syncthreads();

        #pragma unroll
        for (int mt = 0; mt < 2; mt++) {
            float d0[4] = {0.f, 0.f, 0.f, 0.f};
            float d1[4] = {0.f, 0.f, 0.f, 0.f};
            uint32_t ahi = sbase + (uint32_t)(mt * 16 * HSB) + laneoff;
            #pragma unroll
            for (int kk = 0; kk < 8; kk++) {
                uint32_t ah[4];
                ldsm_x4(ah, ahi + kk * 32);
                mma_f16(d0, ah, Fp[kk][0]);
                mma_f16(d1, ah, Fp[kk][1]);
            }
            int row0 = r0 + mt * 16 + g, row1 = row0 + 8;
            int c0 = wid * 16 + 2 * tig;
            if (row0 < cnt) {
                *(uint32_t*)&dst[row0 * H + c0]     = pack_h2(d0[0], d0[1]);
                *(uint32_t*)&dst[row0 * H + c0 + 8] = pack_h2(d1[0], d1[1]);
            }
            if (row1 < cnt) {
                *(uint32_t*)&dst[row1 * H + c0]     = pack_h2(d0[2], d0[3]);
                *(uint32_t*)&dst[row1 * H + c0 + 8] = pack_h2(d1[2], d1[3]);
            }
        }
        __syncthreads();
    } else if (b == SBLOCKS - 1) {
        // g_c = x_graph @ W0[0:2H] + b0 (fp32 accumulate, fp16 store)
        __shared__ float red2[256];
        int col = tid & 127, hh = tid >> 7;
        float acc = 0.f;
        const float* w = W0 + col;
        #pragma unroll 8
        for (int i = hh * 128; i < hh * 128 + 128; i++) acc += xg[i] * w[i * H];
        red2[tid] = acc;
        __syncthreads();
        if (tid < 128) g_c[tid] = __float2half_rn(red2[tid] + red2[tid + 128] + b0[tid]);
        __syncthreads();
    }

    // W1 fragments + output constants (independent of precompute)
    uint32_t Fh[8][2][2];
    {
        int n = wid * 16 + g;
        #pragma unroll
        for (int kk = 0; kk < 8; kk++)
            #pragma unroll
            for (int lnt = 0; lnt < 2; lnt++)
                #pragma unroll
                for (int e = 0; e < 2; e++) {
                    int k0 = kk * 16 + 2 * tig + e * 8;
                    Fh[kk][lnt][e] = pack_h2(W1[k0 * H + n + lnt * 8],
                                             W1[(k0 + 1) * H + n + lnt * 8]);
                }
    }
    float b1c[2][2], w2c[2][2];
    #pragma unroll
    for (int lnt = 0; lnt < 2; lnt++)
        #pragma unroll
        for (int e = 0; e < 2; e++) {
            int col = wid * 16 + lnt * 8 + 2 * tig + e;
            b1c[lnt][e] = b1[col];
            w2c[lnt][e] = W2[col];
        }
    float b2v = b2[0];

    // ================= grid barrier (all 296 blocks resident) ===========
    if (tid == 0) {
        __threadfence();
        atomicAdd(&g_bar, 1);
        while (*(volatile int*)&g_bar < SBLOCKS) __nanosleep(64);
        __threadfence();
    }
    __syncthreads();

    // copy g_c (fp16, 256B) into smem
    if (tid < 16) ((uint4*)cs)[tid] = ((const uint4*)g_c)[tid];
    __syncthreads();

    // ================= PHASE 2: score mainloop ==========================
    float mx = -3.402823466e38f, Z = 0.f, S1 = 0.f;
    int   arg = 0x7fffffff;

    for (int tile = b; tile < NTILES; tile += SBLOCKS) {
        int tbase = tile * 128;

        // gather + fp16 staging: 2 threads/row, half2 adds + relu
        {
            int row = tid >> 1, ch = tid & 1;
            char* rh = smem + row * HSB + ch * 128;
            int grow = tbase + row;
            if (grow < NROWS) {
                int m = m_ids[grow], j = job_idx[grow];
                const uint4* Am = (const uint4*)(g_A + m * H) + ch * 8;
                const uint4* Bj = (const uint4*)(g_B + j * H) + ch * 8;
                const uint4* Cc = (const uint4*)cs + ch * 8;
                #pragma unroll
                for (int c = 0; c < 8; c++) {
                    uint4 a = Am[c], bb = Bj[c], cc = Cc[c];
                    uint4 o;
                    o.x = h2_addmax0(a.x, bb.x, cc.x);
                    o.y = h2_addmax0(a.y, bb.y, cc.y);
                    o.z = h2_addmax0(a.z, bb.z, cc.z);
                    o.w = h2_addmax0(a.w, bb.w, cc.w);
                    *(uint4*)(rh + 16 * c) = o;
                }
            } else {
                uint4 zz = make_uint4(0u, 0u, 0u, 0u);
                #pragma unroll
                for (int c = 0; c < 8; c++) *(uint4*)(rh + 16 * c) = zz;
            }
        }
        __syncthreads();

        // mainloop: 8 m-tiles x 8 k-steps x 2 n-tiles fp16 HMMA
        #pragma unroll 1
        for (int mt = 0; mt < 8; mt++) {
            float d0[4] = {0.f, 0.f, 0.f, 0.f};
            float d1[4] = {0.f, 0.f, 0.f, 0.f};
            uint32_t ahi = sbase + (uint32_t)(mt * 16 * HSB) + laneoff;
            #pragma unroll
            for (int kk = 0; kk < 8; kk++) {
                uint32_t ah[4];
                ldsm_x4(ah, ahi + kk * 32);
                mma_f16(d0, ah, Fh[kk][0]);
                mma_f16(d1, ah, Fh[kk][1]);
            }
            float sg = fmaxf(d0[0] + b1c[0][0], 0.f) * w2c[0][0]
                     + fmaxf(d0[1] + b1c[0][1], 0.f) * w2c[0][1]
                     + fmaxf(d1[0] + b1c[1][0], 0.f) * w2c[1][0]
                     + fmaxf(d1[1] + b1c[1][1], 0.f) * w2c[1][1];
            float sh = fmaxf(d0[2] + b1c[0][0], 0.f) * w2c[0][0]
                     + fmaxf(d0[3] + b1c[0][1], 0.f) * w2c[0][1]
                     + fmaxf(d1[2] + b1c[1][0], 0.f) * w2c[1][0]
                     + fmaxf(d1[3] + b1c[1][1], 0.f) * w2c[1][1];
            sg += __shfl_xor_sync(0xffffffffu, sg, 1);
            sg += __shfl_xor_sync(0xffffffffu, sg, 2);
            sh += __shfl_xor_sync(0xffffffffu, sh, 1);
            sh += __shfl_xor_sync(0xffffffffu, sh, 2);
            if (tig == 0) {
                part[wid * 128 + mt * 16 + g]     = sg;
                part[wid * 128 + mt * 16 + 8 + g] = sh;
            }
        }
        __syncthreads();

        // per-row score + online softmax (threads 0..127)
        if (tid < 128) {
            int grow = tbase + tid;
            if (grow < NROWS) {
                float s = b2v;
                #pragma unroll
                for (int w = 0; w < 8; w++) s += part[w * 128 + tid];
                if (s > mx) {
                    float dd = fmaxf(mx - s, -87.f);
                    float e = expf(dd);
                    S1 = e * (S1 + dd * Z);
                    Z  = e * Z + 1.f;
                    mx = s;
                    arg = grow;
                } else {
                    float t = fmaxf(s - mx, -87.f);
                    float e = expf(t);
                    Z  += e;
                    S1 += t * e;
                }
            }
        }
        __syncthreads();
    }

    // block merge of per-thread softmax states (reuse part region)
    float* smx = part;
    float* sZ  = part + 256;
    float* sS1 = part + 512;
    int*   sarg = (int*)(part + 768);
    smx[tid] = mx; sZ[tid] = Z; sS1[tid] = S1; sarg[tid] = arg;
    __syncthreads();
    for (int s = 128; s; s >>= 1) {
        if (tid < s) {
            float qm = smx[tid + s], qZ = sZ[tid + s], qS = sS1[tid + s];
            int   qa = sarg[tid + s];
            if (qm > smx[tid] || (qm == smx[tid] && qa < sarg[tid])) {
                float d = fmaxf(smx[tid] - qm, -87.f);
                float e = expf(d);
                float Zo = sZ[tid], S1o = sS1[tid];
                sZ[tid]  = qZ + e * Zo;
                sS1[tid] = qS + e * (S1o + d * Zo);
                smx[tid] = qm; sarg[tid] = qa;
            } else {
                float d = fmaxf(qm - smx[tid], -87.f);
                float e = expf(d);
                sZ[tid]  += e * qZ;
                sS1[tid] += e * (qS + d * qZ);
            }
        }
        __syncthreads();
    }
    if (tid == 0) {
        g_wmax[b] = smx[0];
        g_warg[b] = sarg[0];
        g_wZ[b]   = sZ[0];
        g_wS1[b]  = sS1[0];
    }
}

// ---------------- K2: merge 296 block partials ----------------
__global__ void __launch_bounds__(512) finalize_kernel(float* __restrict__ out) {
    __shared__ float smx[512], sZ[512], sS1[512];
    __shared__ int   sarg[512];
    int tid = threadIdx.x;

    float mx = -3.402823466e38f, Z = 0.f, S1 = 0.f;
    int   arg = 0x7fffffff;
    if (tid < NWTOT) { mx = g_wmax[tid]; Z = g_wZ[tid]; S1 = g_wS1[tid]; arg = g_warg[tid]; }
    smx[tid] = mx; sarg[tid] = arg; sZ[tid] = Z; sS1[tid] = S1;
    __syncthreads();

    for (int s = 256; s; s >>= 1) {
        if (tid < s) {
            float qm = smx[tid + s], qZ = sZ[tid + s], qS = sS1[tid + s];
            int   qa = sarg[tid + s];
            if (qm > smx[tid] || (qm == smx[tid] && qa < sarg[tid])) {
                float d = fmaxf(smx[tid] - qm, -87.f);
                float e = expf(d);
                float Zo = sZ[tid], S1o = sS1[tid];
                sZ[tid]  = qZ + e * Zo;
                sS1[tid] = qS + e * (S1o + d * Zo);
                smx[tid] = qm; sarg[tid] = qa;
            } else {
                float d = fmaxf(qm - smx[tid], -87.f);
                float e = expf(d);
                sZ[tid]  += e * qZ;
                sS1[tid] += e * (qS + d * qZ);
            }
        }
        __syncthreads();
    }

    if (tid == 0) {
        float Zf = sZ[0], S1f = sS1[0];
        float logZ = logf(Zf);
        out[0] = (float)sarg[0];
        out[1] = 1.0f / Zf;          // p[idx]  (t=0 at argmax)
        out[2] = -logZ;              // logp[idx]
        out[3] = logZ - S1f / Zf;    // entropy
    }
}

// ---------------- launch ----------------
extern "C" void kernel_launch(void* const* d_in, const int* in_sizes, int n_in,
                              void* d_out, int out_size) {
    const float* x_graph = (const float*)d_in[0];
    const float* x_m     = (const float*)d_in[1];
    const float* x_job   = (const float*)d_in[2];
    const int*   m_ids   = (const int*)  d_in[3];
    const int*   job_idx = (const int*)  d_in[4];
    const float* W0      = (const float*)d_in[5];
    const float* b0      = (const float*)d_in[6];
    const float* W1      = (const float*)d_in[7];
    const float* b1      = (const float*)d_in[8];
    const float* W2      = (const float*)d_in[9];
    const float* b2      = (const float*)d_in[10];
    float* out = (float*)d_out;

    cudaFuncSetAttribute(score_kernel,
                         cudaFuncAttributeMaxDynamicSharedMemorySize, SMEM_SZ);

    zero_bar_kernel<<<1, 1>>>();
    score_kernel<<<SBLOCKS, 256, SMEM_SZ>>>(x_graph, x_m, x_job, W0, b0,
                                            m_ids, job_idx, W1, b1, W2, b2);
    finalize_kernel<<<1, 512>>>(out);
}

// round 14
// speedup vs baseline: 1.4113x; 1.0078x over previous
#include <cuda_runtime.h>
#include <cuda_fp16.h>
#include <cstdint>

#define H        128
#define NROWS    200000
#define NTILES   ((NROWS + 127) / 128)   // 1563
#define M_NODES  1000
#define J_NODES  5000
#define SBLOCKS  296                     // 2 blocks/SM, exactly resident
#define NWTOT    SBLOCKS

// staged row stride: 272B -> 16B-aligned ldmatrix rows, bank shift 4.
#define HSB       272
#define PART_OFF  (128 * HSB)            // 34816
#define SMEM_SZ   (PART_OFF + 4096)      // 38912

// precompute prologue tiling (32 rows per block)
#define NT_PM     32                     // ceil(1000/32)
#define NT_PJ     157                    // ceil(5000/32)
#define NT_TOT    (NT_PM + NT_PJ)        // 189

// ---------------- device scratch ----------------
__device__ __align__(16) __half g_A[M_NODES * H];   // holds A + c (folded)
__device__ __align__(16) __half g_B[J_NODES * H];
__device__ int   g_bar;                  // monotonic ticket barrier
__device__ float g_wmax[NWTOT];
__device__ int   g_warg[NWTOT];
__device__ float g_wZ[NWTOT];
__device__ float g_wS1[NWTOT];

// ---------------- PTX helpers (generic ISA only) ----------------
__device__ __forceinline__ uint32_t smem_u32(const void* p) {
    uint32_t a;
    asm("{ .reg .u64 t; cvta.to.shared.u64 t, %1; cvt.u32.u64 %0, t; }" : "=r"(a) : "l"(p));
    return a;
}
__device__ __forceinline__ void ldsm_x4(uint32_t* r, uint32_t addr) {
    asm volatile("ldmatrix.sync.aligned.m8n8.x4.shared.b16 {%0,%1,%2,%3}, [%4];"
        : "=r"(r[0]), "=r"(r[1]), "=r"(r[2]), "=r"(r[3]) : "r"(addr));
}
__device__ __forceinline__ void mma_f16(float* d, const uint32_t* a, const uint32_t* b) {
    asm volatile("mma.sync.aligned.m16n8k16.row.col.f32.f16.f16.f32 "
        "{%0,%1,%2,%3}, {%4,%5,%6,%7}, {%8,%9}, {%0,%1,%2,%3};"
        : "+f"(d[0]), "+f"(d[1]), "+f"(d[2]), "+f"(d[3])
        : "r"(a[0]), "r"(a[1]), "r"(a[2]), "r"(a[3]), "r"(b[0]), "r"(b[1]));
}
__device__ __forceinline__ uint32_t pack_h2(float lo, float hi) {
    __half2 t = __floats2half2_rn(lo, hi);
    return *(uint32_t*)&t;
}
// fused half2 add + relu via fma.rn.relu.f16x2 (sm_80+ modifier):
// relu(a*1.0 + b), ONE = packed (1.0h, 1.0h)
__device__ __forceinline__ uint32_t h2_addrelu(uint32_t a, uint32_t b) {
    uint32_t r;
    const uint32_t ONE = 0x3C003C00u;
    asm("fma.rn.relu.f16x2 %0, %1, %2, %3;" : "=r"(r) : "r"(a), "r"(ONE), "r"(b));
    return r;
}

// ticket grid barrier: monotonic counter, graph-replay safe (no reset)
__device__ __forceinline__ void grid_bar(int tid) {
    if (tid == 0) {
        __threadfence();
        int ticket = atomicAdd(&g_bar, 1);
        int target = (ticket / SBLOCKS + 1) * SBLOCKS;
        while (*(volatile int*)&g_bar < target) __nanosleep(32);
        __threadfence();
    }
    __syncthreads();
}

// ---------------- fused precompute + score + finalize (persistent) --------
__global__ void __launch_bounds__(256, 2) score_kernel(
        const float* __restrict__ xg,    const float* __restrict__ xm,
        const float* __restrict__ xj,    const float* __restrict__ W0,
        const float* __restrict__ b0,
        const int*   __restrict__ m_ids, const int* __restrict__ job_idx,
        const float* __restrict__ W1,    const float* __restrict__ b1,
        const float* __restrict__ W2,    const float* __restrict__ b2,
        float* __restrict__ out) {
    extern __shared__ char smem[];
    uint32_t sbase = smem_u32(smem);
    float* part = (float*)(smem + PART_OFF);   // 1024 floats scratch

    int tid  = threadIdx.x;
    int lane = tid & 31;
    int wid  = tid >> 5;
    int g    = lane >> 2;
    int tig  = lane & 3;
    int b    = blockIdx.x;

    uint32_t laneoff = (uint32_t)(((lane & 7) + ((lane >> 3) & 1) * 8) * HSB
                                  + ((lane >> 4) & 1) * 16);

    // ================= PHASE 1: distributed precompute =================
    if (b < NT_TOT) {
        const float* src; __half* dst; int r0, cnt, woff;
        bool isA = (b < NT_PM);
        if (isA) { src = xm; dst = g_A; r0 = b * 32;           cnt = M_NODES; woff = 2 * H; }
        else     { src = xj; dst = g_B; r0 = (b - NT_PM) * 32; cnt = J_NODES; woff = 3 * H; }

        // W0 fragments fp16: warp owns 16 outcols
        uint32_t Fp[8][2][2];
        {
            int n = wid * 16 + g;
            #pragma unroll
            for (int kk = 0; kk < 8; kk++)
                #pragma unroll
                for (int lnt = 0; lnt < 2; lnt++)
                    #pragma unroll
                    for (int e = 0; e < 2; e++) {
                        int k0 = kk * 16 + 2 * tig + e * 8;
                        Fp[kk][lnt][e] = pack_h2(W0[(woff + k0) * H + n + lnt * 8],
                                                 W0[(woff + k0 + 1) * H + n + lnt * 8]);
                    }
        }

        // A-blocks: compute c = xg @ W0[0:2H] + b0 redundantly (fp32)
        float* cpart = part;           // [256]
        float* cfin  = part + 256;     // [128]
        if (isA) {
            int col = tid & 127, hh = tid >> 7;
            float acc = 0.f;
            const float* w = W0 + col;
            #pragma unroll 8
            for (int i = hh * 128; i < hh * 128 + 128; i++) acc += xg[i] * w[i * H];
            cpart[tid] = acc;
        }

        // stage 32 x-rows as fp16 (8 threads/row, 16 halves each)
        {
            int row = tid >> 3, p = tid & 7;
            char* rh = smem + row * HSB;
            int r = r0 + row;
            if (r < cnt) {
                const float4* xr = (const float4*)(src + r * H) + p * 4;
                float4 v0 = xr[0], v1 = xr[1], v2 = xr[2], v3 = xr[3];
                uint4 o0, o1;
                o0.x = pack_h2(v0.x, v0.y); o0.y = pack_h2(v0.z, v0.w);
                o0.z = pack_h2(v1.x, v1.y); o0.w = pack_h2(v1.z, v1.w);
                o1.x = pack_h2(v2.x, v2.y); o1.y = pack_h2(v2.z, v2.w);
                o1.z = pack_h2(v3.x, v3.y); o1.w = pack_h2(v3.z, v3.w);
                *(uint4*)(rh + p * 32)      = o0;
                *(uint4*)(rh + p * 32 + 16) = o1;
            } else {
                uint4 zz = make_uint4(0u, 0u, 0u, 0u);
                *(uint4*)(rh + p * 32)      = zz;
                *(uint4*)(rh + p * 32 + 16) = zz;
            }
        }
        __syncthreads();
        if (isA && tid < 128) cfin[tid] = cpart[tid] + cpart[tid + 128] + b0[tid];
        __syncthreads();

        #pragma unroll
        for (int mt = 0; mt < 2; mt++) {
            float d0[4] = {0.f, 0.f, 0.f, 0.f};
            float d1[4] = {0.f, 0.f, 0.f, 0.f};
            uint32_t ahi = sbase + (uint32_t)(mt * 16 * HSB) + laneoff;
            #pragma unroll
            for (int kk = 0; kk < 8; kk++) {
                uint32_t ah[4];
                ldsm_x4(ah, ahi + kk * 32);
                mma_f16(d0, ah, Fp[kk][0]);
                mma_f16(d1, ah, Fp[kk][1]);
            }
            int row0 = r0 + mt * 16 + g, row1 = row0 + 8;
            int c0 = wid * 16 + 2 * tig;
            float a0 = 0.f, a1 = 0.f, a2 = 0.f, a3 = 0.f;
            if (isA) {
                a0 = cfin[c0]; a1 = cfin[c0 + 1];
                a2 = cfin[c0 + 8]; a3 = cfin[c0 + 9];
            }
            if (row0 < cnt) {
                *(uint32_t*)&dst[row0 * H + c0]     = pack_h2(d0[0] + a0, d0[1] + a1);
                *(uint32_t*)&dst[row0 * H + c0 + 8] = pack_h2(d1[0] + a2, d1[1] + a3);
            }
            if (row1 < cnt) {
                *(uint32_t*)&dst[row1 * H + c0]     = pack_h2(d0[2] + a0, d0[3] + a1);
                *(uint32_t*)&dst[row1 * H + c0 + 8] = pack_h2(d1[2] + a2, d1[3] + a3);
            }
        }
        __syncthreads();
    }

    // W1 fragments + output constants (independent of precompute)
    uint32_t Fh[8][2][2];
    {
        int n = wid * 16 + g;
        #pragma unroll
        for (int kk = 0; kk < 8; kk++)
            #pragma unroll
            for (int lnt = 0; lnt < 2; lnt++)
                #pragma unroll
                for (int e = 0; e < 2; e++) {
                    int k0 = kk * 16 + 2 * tig + e * 8;
                    Fh[kk][lnt][e] = pack_h2(W1[k0 * H + n + lnt * 8],
                                             W1[(k0 + 1) * H + n + lnt * 8]);
                }
    }
    float b1c[2][2], w2c[2][2];
    #pragma unroll
    for (int lnt = 0; lnt < 2; lnt++)
        #pragma unroll
        for (int e = 0; e < 2; e++) {
            int col = wid * 16 + lnt * 8 + 2 * tig + e;
            b1c[lnt][e] = b1[col];
            w2c[lnt][e] = W2[col];
        }
    float b2v = b2[0];

    // ================= grid barrier #1 ==================================
    grid_bar(tid);

    // ================= PHASE 2: score mainloop ==========================
    float mx = -3.402823466e38f, Z = 0.f, S1 = 0.f;
    int   arg = 0x7fffffff;

    for (int tile = b; tile < NTILES; tile += SBLOCKS) {
        int tbase = tile * 128;

        // gather + fused fma.relu fp16 staging: 2 threads/row
        {
            int row = tid >> 1, ch = tid & 1;
            char* rh = smem + row * HSB + ch * 128;
            int grow = tbase + row;
            if (grow < NROWS) {
                int m = m_ids[grow], j = job_idx[grow];
                const uint4* Am = (const uint4*)(g_A + m * H) + ch * 8;
                const uint4* Bj = (const uint4*)(g_B + j * H) + ch * 8;
                #pragma unroll
                for (int c = 0; c < 8; c++) {
                    uint4 a = Am[c], bb = Bj[c], o;
                    o.x = h2_addrelu(a.x, bb.x);
                    o.y = h2_addrelu(a.y, bb.y);
                    o.z = h2_addrelu(a.z, bb.z);
                    o.w = h2_addrelu(a.w, bb.w);
                    *(uint4*)(rh + 16 * c) = o;
                }
            } else {
                uint4 zz = make_uint4(0u, 0u, 0u, 0u);
                #pragma unroll
                for (int c = 0; c < 8; c++) *(uint4*)(rh + 16 * c) = zz;
            }
        }
        __syncthreads();

        // mainloop: 8 m-tiles x 8 k-steps x 2 n-tiles fp16 HMMA
        #pragma unroll 1
        for (int mt = 0; mt < 8; mt++) {
            float d0[4] = {0.f, 0.f, 0.f, 0.f};
            float d1[4] = {0.f, 0.f, 0.f, 0.f};
            uint32_t ahi = sbase + (uint32_t)(mt * 16 * HSB) + laneoff;
            #pragma unroll
            for (int kk = 0; kk < 8; kk++) {
                uint32_t ah[4];
                ldsm_x4(ah, ahi + kk * 32);
                mma_f16(d0, ah, Fh[kk][0]);
                mma_f16(d1, ah, Fh[kk][1]);
            }
            float sg = fmaxf(d0[0] + b1c[0][0], 0.f) * w2c[0][0]
                     + fmaxf(d0[1] + b1c[0][1], 0.f) * w2c[0][1]
                     + fmaxf(d1[0] + b1c[1][0], 0.f) * w2c[1][0]
                     + fmaxf(d1[1] + b1c[1][1], 0.f) * w2c[1][1];
            float sh = fmaxf(d0[2] + b1c[0][0], 0.f) * w2c[0][0]
                     + fmaxf(d0[3] + b1c[0][1], 0.f) * w2c[0][1]
                     + fmaxf(d1[2] + b1c[1][0], 0.f) * w2c[1][0]
                     + fmaxf(d1[3] + b1c[1][1], 0.f) * w2c[1][1];
            sg += __shfl_xor_sync(0xffffffffu, sg, 1);
            sg += __shfl_xor_sync(0xffffffffu, sg, 2);
            sh += __shfl_xor_sync(0xffffffffu, sh, 1);
            sh += __shfl_xor_sync(0xffffffffu, sh, 2);
            if (tig == 0) {
                part[wid * 128 + mt * 16 + g]     = sg;
                part[wid * 128 + mt * 16 + 8 + g] = sh;
            }
        }
        __syncthreads();

        // per-row score + online softmax (threads 0..127)
        if (tid < 128) {
            int grow = tbase + tid;
            if (grow < NROWS) {
                float s = b2v;
                #pragma unroll
                for (int w = 0; w < 8; w++) s += part[w * 128 + tid];
                if (s > mx) {
                    float dd = fmaxf(mx - s, -87.f);
                    float e = expf(dd);
                    S1 = e * (S1 + dd * Z);
                    Z  = e * Z + 1.f;
                    mx = s;
                    arg = grow;
                } else {
                    float t = fmaxf(s - mx, -87.f);
                    float e = expf(t);
                    Z  += e;
                    S1 += t * e;
                }
            }
        }
        __syncthreads();
    }

    // block merge of per-thread softmax states (reuse part region)
    float* smx = part;
    float* sZ  = part + 256;
    float* sS1 = part + 512;
    int*   sarg = (int*)(part + 768);
    smx[tid] = mx; sZ[tid] = Z; sS1[tid] = S1; sarg[tid] = arg;
    __syncthreads();
    for (int s = 128; s; s >>= 1) {
        if (tid < s) {
            float qm = smx[tid + s], qZ = sZ[tid + s], qS = sS1[tid + s];
            int   qa = sarg[tid + s];
            if (qm > smx[tid] || (qm == smx[tid] && qa < sarg[tid])) {
                float d = fmaxf(smx[tid] - qm, -87.f);
                float e = expf(d);
                float Zo = sZ[tid], S1o = sS1[tid];
                sZ[tid]  = qZ + e * Zo;
                sS1[tid] = qS + e * (S1o + d * Zo);
                smx[tid] = qm; sarg[tid] = qa;
            } else {
                float d = fmaxf(qm - smx[tid], -87.f);
                float e = expf(d);
                sZ[tid]  += e * qZ;
                sS1[tid] += e * (qS + d * qZ);
            }
        }
        __syncthreads();
    }
    if (tid == 0) {
        g_wmax[b] = smx[0];
        g_warg[b] = sarg[0];
        g_wZ[b]   = sZ[0];
        g_wS1[b]  = sS1[0];
    }

    // ================= grid barrier #2 + inline finalize ================
    grid_bar(tid);
    if (b != 0) return;

    float fmx = -3.402823466e38f, fZ = 0.f, fS1 = 0.f;
    int   farg = 0x7fffffff;
    for (int i = tid; i < NWTOT; i += 256) {
        float qm = g_wmax[i], qZ = g_wZ[i], qS = g_wS1[i];
        int   qa = g_warg[i];
        if (qm > fmx || (qm == fmx && qa < farg)) {
            float d = fmaxf(fmx - qm, -87.f);
            float e = expf(d);
            float Zo = fZ, S1o = fS1;
            fZ  = qZ + e * Zo;
            fS1 = qS + e * (S1o + d * Zo);
            fmx = qm; farg = qa;
        } else {
            float d = fmaxf(qm - fmx, -87.f);
            float e = expf(d);
            fZ  += e * qZ;
            fS1 += e * (qS + d * qZ);
        }
    }
    __syncthreads();
    smx[tid] = fmx; sarg[tid] = farg; sZ[tid] = fZ; sS1[tid] = fS1;
    __syncthreads();
    for (int s = 128; s; s >>= 1) {
        if (tid < s) {
            float qm = smx[tid + s], qZ = sZ[tid + s], qS = sS1[tid + s];
            int   qa = sarg[tid + s];
            if (qm > smx[tid] || (qm == smx[tid] && qa < sarg[tid])) {
                float d = fmaxf(smx[tid] - qm, -87.f);
                float e = expf(d);
                float Zo = sZ[tid], S1o = sS1[tid];
                sZ[tid]  = qZ + e * Zo;
                sS1[tid] = qS + e * (S1o + d * Zo);
                smx[tid] = qm; sarg[tid] = qa;
            } else {
                float d = fmaxf(qm - smx[tid], -87.f);
                float e = expf(d);
                sZ[tid]  += e * qZ;
                sS1[tid] += e * (qS + d * qZ);
            }
        }
        __syncthreads();
    }
    if (tid == 0) {
        float Zf = sZ[0], S1f = sS1[0];
        float logZ = logf(Zf);
        out[0] = (float)sarg[0];
        out[1] = 1.0f / Zf;          // p[idx]  (t=0 at argmax)
        out[2] = -logZ;              // logp[idx]
        out[3] = logZ - S1f / Zf;    // entropy
    }
}

// ---------------- launch ----------------
extern "C" void kernel_launch(void* const* d_in, const int* in_sizes, int n_in,
                              void* d_out, int out_size) {
    const float* x_graph = (const float*)d_in[0];
    const float* x_m     = (const float*)d_in[1];
    const float* x_job   = (const float*)d_in[2];
    const int*   m_ids   = (const int*)  d_in[3];
    const int*   job_idx = (const int*)  d_in[4];
    const float* W0      = (const float*)d_in[5];
    const float* b0      = (const float*)d_in[6];
    const float* W1      = (const float*)d_in[7];
    const float* b1      = (const float*)d_in[8];
    const float* W2      = (const float*)d_in[9];
    const float* b2      = (const float*)d_in[10];
    float* out = (float*)d_out;

    cudaFuncSetAttribute(score_kernel,
                         cudaFuncAttributeMaxDynamicSharedMemorySize, SMEM_SZ);

    score_kernel<<<SBLOCKS, 256, SMEM_SZ>>>(x_graph, x_m, x_job, W0, b0,
                                            m_ids, job_idx, W1, b1, W2, b2, out);
}

// round 15
// speedup vs baseline: 1.5507x; 1.0988x over previous
#include <cuda_runtime.h>
#include <cuda_fp16.h>
#include <cstdint>

#define H        128
#define NROWS    200000
#define NTILES   ((NROWS + 127) / 128)   // 1563
#define M_NODES  1000
#define J_NODES  5000
#define SBLOCKS  148                     // 1 block/SM (512 thr), all resident
#define NWTOT    SBLOCKS

// staged row stride: 272B -> 16B-aligned ldmatrix rows, bank shift 4.
#define HSB       272
#define PART_OFF  (128 * HSB)            // 34816
#define SMEM_SZ   (PART_OFF + 4096)      // 38912 (scratch = 1024 floats)

// precompute tiling: 64 rows per block
#define NT_PM     16                     // ceil(1000/64)
#define NT_PJ     79                     // ceil(5000/64)
#define NT_TOT    95

// ---------------- device scratch ----------------
__device__ __align__(16) __half g_A[M_NODES * H];   // holds A + c (folded)
__device__ __align__(16) __half g_B[J_NODES * H];
__device__ int   g_bar;                  // monotonic ticket barrier
__device__ float g_wmax[NWTOT];
__device__ int   g_warg[NWTOT];
__device__ float g_wZ[NWTOT];
__device__ float g_wS1[NWTOT];

// ---------------- PTX helpers (generic ISA only) ----------------
__device__ __forceinline__ uint32_t smem_u32(const void* p) {
    uint32_t a;
    asm("{ .reg .u64 t; cvta.to.shared.u64 t, %1; cvt.u32.u64 %0, t; }" : "=r"(a) : "l"(p));
    return a;
}
__device__ __forceinline__ void ldsm_x4(uint32_t* r, uint32_t addr) {
    asm volatile("ldmatrix.sync.aligned.m8n8.x4.shared.b16 {%0,%1,%2,%3}, [%4];"
        : "=r"(r[0]), "=r"(r[1]), "=r"(r[2]), "=r"(r[3]) : "r"(addr));
}
__device__ __forceinline__ void mma_f16(float* d, const uint32_t* a, const uint32_t* b) {
    asm volatile("mma.sync.aligned.m16n8k16.row.col.f32.f16.f16.f32 "
        "{%0,%1,%2,%3}, {%4,%5,%6,%7}, {%8,%9}, {%0,%1,%2,%3};"
        : "+f"(d[0]), "+f"(d[1]), "+f"(d[2]), "+f"(d[3])
        : "r"(a[0]), "r"(a[1]), "r"(a[2]), "r"(a[3]), "r"(b[0]), "r"(b[1]));
}
__device__ __forceinline__ uint32_t pack_h2(float lo, float hi) {
    __half2 t = __floats2half2_rn(lo, hi);
    return *(uint32_t*)&t;
}
// fused half2 add + relu: relu(a*1.0 + b)
__device__ __forceinline__ uint32_t h2_addrelu(uint32_t a, uint32_t b) {
    uint32_t r;
    const uint32_t ONE = 0x3C003C00u;
    asm("fma.rn.relu.f16x2 %0, %1, %2, %3;" : "=r"(r) : "r"(a), "r"(ONE), "r"(b));
    return r;
}

// ticket grid barrier: monotonic counter, graph-replay safe (no reset)
__device__ __forceinline__ void grid_bar(int tid) {
    if (tid == 0) {
        __threadfence();
        int ticket = atomicAdd(&g_bar, 1);
        int target = (ticket / SBLOCKS + 1) * SBLOCKS;
        while (*(volatile int*)&g_bar < target) __nanosleep(32);
        __threadfence();
    }
    __syncthreads();
}

// ---------------- fused precompute + score + finalize (persistent) --------
__global__ void __launch_bounds__(512, 1) score_kernel(
        const float* __restrict__ xg,    const float* __restrict__ xm,
        const float* __restrict__ xj,    const float* __restrict__ W0,
        const float* __restrict__ b0,
        const int*   __restrict__ m_ids, const int* __restrict__ job_idx,
        const float* __restrict__ W1,    const float* __restrict__ b1,
        const float* __restrict__ W2,    const float* __restrict__ b2,
        float* __restrict__ out) {
    extern __shared__ char smem[];
    uint32_t sbase = smem_u32(smem);
    float* scratch = (float*)(smem + PART_OFF);   // 1024 floats

    int tid  = threadIdx.x;
    int lane = tid & 31;
    int wid  = tid >> 5;          // 0..15
    int g    = lane >> 2;         // 0..7
    int tig  = lane & 3;          // 0..3
    int rh   = wid >> 2;          // 0..3  (row-half group)
    int cg   = wid & 3;           // 0..3  (col group: 32 cols)
    int b    = blockIdx.x;

    uint32_t laneoff = (uint32_t)(((lane & 7) + ((lane >> 3) & 1) * 8) * HSB
                                  + ((lane >> 4) & 1) * 16);

    // ================= PHASE 1: distributed precompute (64 rows/block) ====
    if (b < NT_TOT) {
        const float* src; __half* dst; int r0, cnt, woff;
        bool isA = (b < NT_PM);
        if (isA) { src = xm; dst = g_A; r0 = b * 64;           cnt = M_NODES; woff = 2 * H; }
        else     { src = xj; dst = g_B; r0 = (b - NT_PM) * 64; cnt = J_NODES; woff = 3 * H; }

        // W0 fragments fp16: warp owns 32 outcols (4 n-tiles)
        uint32_t Fp[8][4][2];
        {
            int n = cg * 32 + g;
            #pragma unroll
            for (int kk = 0; kk < 8; kk++)
                #pragma unroll
                for (int t = 0; t < 4; t++)
                    #pragma unroll
                    for (int e = 0; e < 2; e++) {
                        int k0 = kk * 16 + 2 * tig + e * 8;
                        Fp[kk][t][e] = pack_h2(W0[(woff + k0) * H + n + t * 8],
                                               W0[(woff + k0 + 1) * H + n + t * 8]);
                    }
        }

        // A-blocks: compute c = xg @ W0[0:2H] + b0 redundantly (fp32)
        float* cpart = scratch;          // [512]
        float* cfin  = scratch + 512;    // [128]
        if (isA) {
            int col = tid & 127, hh = tid >> 7;   // hh 0..3 covers 64 rows each
            float acc = 0.f;
            const float* w = W0 + col;
            #pragma unroll 8
            for (int i = hh * 64; i < hh * 64 + 64; i++) acc += xg[i] * w[i * H];
            cpart[tid] = acc;
        }

        // stage 64 x-rows as fp16 (8 threads/row)
        {
            int row = tid >> 3, p = tid & 7;
            char* rhp = smem + row * HSB;
            int r = r0 + row;
            if (r < cnt) {
                const float4* xr = (const float4*)(src + r * H) + p * 4;
                float4 v0 = xr[0], v1 = xr[1], v2 = xr[2], v3 = xr[3];
                uint4 o0, o1;
                o0.x = pack_h2(v0.x, v0.y); o0.y = pack_h2(v0.z, v0.w);
                o0.z = pack_h2(v1.x, v1.y); o0.w = pack_h2(v1.z, v1.w);
                o1.x = pack_h2(v2.x, v2.y); o1.y = pack_h2(v2.z, v2.w);
                o1.z = pack_h2(v3.x, v3.y); o1.w = pack_h2(v3.z, v3.w);
                *(uint4*)(rhp + p * 32)      = o0;
                *(uint4*)(rhp + p * 32 + 16) = o1;
            } else {
                uint4 zz = make_uint4(0u, 0u, 0u, 0u);
                *(uint4*)(rhp + p * 32)      = zz;
                *(uint4*)(rhp + p * 32 + 16) = zz;
            }
        }
        __syncthreads();
        if (isA && tid < 128)
            cfin[tid] = cpart[tid] + cpart[tid + 128] + cpart[tid + 256]
                      + cpart[tid + 384] + b0[tid];
        __syncthreads();

        // warp computes m-tile = rh (rows r0+16rh..), n-tiles 4cg..4cg+3
        {
            float d[4][4];
            #pragma unroll
            for (int t = 0; t < 4; t++)
                d[t][0] = d[t][1] = d[t][2] = d[t][3] = 0.f;
            uint32_t ahi = sbase + (uint32_t)(rh * 16 * HSB) + laneoff;
            #pragma unroll
            for (int kk = 0; kk < 8; kk++) {
                uint32_t ah[4];
                ldsm_x4(ah, ahi + kk * 32);
                #pragma unroll
                for (int t = 0; t < 4; t++) mma_f16(d[t], ah, Fp[kk][t]);
            }
            int row0 = r0 + rh * 16 + g, row1 = row0 + 8;
            #pragma unroll
            for (int t = 0; t < 4; t++) {
                int c0 = cg * 32 + t * 8 + 2 * tig;
                float a0 = 0.f, a1 = 0.f;
                if (isA) { a0 = cfin[c0]; a1 = cfin[c0 + 1]; }
                if (row0 < cnt)
                    *(uint32_t*)&dst[row0 * H + c0] = pack_h2(d[t][0] + a0, d[t][1] + a1);
                if (row1 < cnt)
                    *(uint32_t*)&dst[row1 * H + c0] = pack_h2(d[t][2] + a0, d[t][3] + a1);
            }
        }
        __syncthreads();
    }

    // W1 fragments: warp owns 32 outcols (4 n-tiles) — 64 regs
    uint32_t Fh[8][4][2];
    {
        int n = cg * 32 + g;
        #pragma unroll
        for (int kk = 0; kk < 8; kk++)
            #pragma unroll
            for (int t = 0; t < 4; t++)
                #pragma unroll
                for (int e = 0; e < 2; e++) {
                    int k0 = kk * 16 + 2 * tig + e * 8;
                    Fh[kk][t][e] = pack_h2(W1[k0 * H + n + t * 8],
                                           W1[(k0 + 1) * H + n + t * 8]);
                }
    }
    float b1c[4][2], w2c[4][2];
    #pragma unroll
    for (int t = 0; t < 4; t++)
        #pragma unroll
        for (int e = 0; e < 2; e++) {
            int col = cg * 32 + t * 8 + 2 * tig + e;
            b1c[t][e] = b1[col];
            w2c[t][e] = W2[col];
        }
    float b2v = b2[0];

    // ================= grid barrier #1 ==================================
    grid_bar(tid);

    // ================= PHASE 2: score mainloop ==========================
    float mx = -3.402823466e38f, Z = 0.f, S1 = 0.f;
    int   arg = 0x7fffffff;
    float* part = scratch;    // [4][128]

    for (int tile = b; tile < NTILES; tile += SBLOCKS) {
        int tbase = tile * 128;

        // gather + fused fma.relu fp16 staging: 4 threads/row (conflict-free)
        {
            int row = tid >> 2, q = tid & 3;
            char* rhp = smem + row * HSB;
            int grow = tbase + row;
            if (grow < NROWS) {
                int m = m_ids[grow], j = job_idx[grow];
                const uint4* Am = (const uint4*)(g_A + m * H) + q * 4;
                const uint4* Bj = (const uint4*)(g_B + j * H) + q * 4;
                #pragma unroll
                for (int c = 0; c < 4; c++) {
                    uint4 a = Am[c], bb = Bj[c], o;
                    o.x = h2_addrelu(a.x, bb.x);
                    o.y = h2_addrelu(a.y, bb.y);
                    o.z = h2_addrelu(a.z, bb.z);
                    o.w = h2_addrelu(a.w, bb.w);
                    *(uint4*)(rhp + (q * 4 + c) * 16) = o;
                }
            } else {
                uint4 zz = make_uint4(0u, 0u, 0u, 0u);
                #pragma unroll
                for (int c = 0; c < 4; c++) *(uint4*)(rhp + (q * 4 + c) * 16) = zz;
            }
        }
        __syncthreads();

        // mainloop: warp does 2 m-tiles x 4 n-tiles (reuse 4 per ldsm)
        #pragma unroll
        for (int half = 0; half < 2; half++) {
            int mt = rh * 2 + half;
            float d[4][4];
            #pragma unroll
            for (int t = 0; t < 4; t++)
                d[t][0] = d[t][1] = d[t][2] = d[t][3] = 0.f;
            uint32_t ahi = sbase + (uint32_t)(mt * 16 * HSB) + laneoff;
            #pragma unroll
            for (int kk = 0; kk < 8; kk++) {
                uint32_t ah[4];
                ldsm_x4(ah, ahi + kk * 32);
                #pragma unroll
                for (int t = 0; t < 4; t++) mma_f16(d[t], ah, Fh[kk][t]);
            }
            // rows mt*16+g / +8: partial over this warp's 32 outcols
            float sg = 0.f, sh = 0.f;
            #pragma unroll
            for (int t = 0; t < 4; t++) {
                sg += fmaxf(d[t][0] + b1c[t][0], 0.f) * w2c[t][0]
                    + fmaxf(d[t][1] + b1c[t][1], 0.f) * w2c[t][1];
                sh += fmaxf(d[t][2] + b1c[t][0], 0.f) * w2c[t][0]
                    + fmaxf(d[t][3] + b1c[t][1], 0.f) * w2c[t][1];
            }
            sg += __shfl_xor_sync(0xffffffffu, sg, 1);
            sg += __shfl_xor_sync(0xffffffffu, sg, 2);
            sh += __shfl_xor_sync(0xffffffffu, sh, 1);
            sh += __shfl_xor_sync(0xffffffffu, sh, 2);
            if (tig == 0) {
                part[cg * 128 + mt * 16 + g]     = sg;
                part[cg * 128 + mt * 16 + 8 + g] = sh;
            }
        }
        __syncthreads();

        // per-row score + online softmax (threads 0..127)
        if (tid < 128) {
            int grow = tbase + tid;
            if (grow < NROWS) {
                float s = b2v + part[tid] + part[128 + tid]
                              + part[256 + tid] + part[384 + tid];
                if (s > mx) {
                    float dd = fmaxf(mx - s, -87.f);
                    float e = expf(dd);
                    S1 = e * (S1 + dd * Z);
                    Z  = e * Z + 1.f;
                    mx = s;
                    arg = grow;
                } else {
                    float t = fmaxf(s - mx, -87.f);
                    float e = expf(t);
                    Z  += e;
                    S1 += t * e;
                }
            }
        }
        __syncthreads();
    }

    // block merge of per-thread softmax states (threads 0..127 hold state)
    float* smx = scratch;          // [128]
    float* sZ  = scratch + 128;
    float* sS1 = scratch + 256;
    int*   sarg = (int*)(scratch + 384);
    if (tid < 128) { smx[tid] = mx; sZ[tid] = Z; sS1[tid] = S1; sarg[tid] = arg; }
    __syncthreads();
    for (int s = 64; s; s >>= 1) {
        if (tid < s) {
            float qm = smx[tid + s], qZ = sZ[tid + s], qS = sS1[tid + s];
            int   qa = sarg[tid + s];
            if (qm > smx[tid] || (qm == smx[tid] && qa < sarg[tid])) {
                float d = fmaxf(smx[tid] - qm, -87.f);
                float e = expf(d);
                float Zo = sZ[tid], S1o = sS1[tid];
                sZ[tid]  = qZ + e * Zo;
                sS1[tid] = qS + e * (S1o + d * Zo);
                smx[tid] = qm; sarg[tid] = qa;
            } else {
                float d = fmaxf(qm - smx[tid], -87.f);
                float e = expf(d);
                sZ[tid]  += e * qZ;
                sS1[tid] += e * (qS + d * qZ);
            }
        }
        __syncthreads();
    }
    if (tid == 0) {
        g_wmax[b] = smx[0];
        g_warg[b] = sarg[0];
        g_wZ[b]   = sZ[0];
        g_wS1[b]  = sS1[0];
    }

    // ================= grid barrier #2 + inline finalize ================
    grid_bar(tid);
    if (b != 0) return;

    float fmx = -3.402823466e38f, fZ = 0.f, fS1 = 0.f;
    int   farg = 0x7fffffff;
    if (tid < 128) {
        for (int i = tid; i < NWTOT; i += 128) {
            float qm = g_wmax[i], qZ = g_wZ[i], qS = g_wS1[i];
            int   qa = g_warg[i];
            if (qm > fmx || (qm == fmx && qa < farg)) {
                float d = fmaxf(fmx - qm, -87.f);
                float e = expf(d);
                float Zo = fZ, S1o = fS1;
                fZ  = qZ + e * Zo;
                fS1 = qS + e * (S1o + d * Zo);
                fmx = qm; farg = qa;
            } else {
                float d = fmaxf(qm - fmx, -87.f);
                float e = expf(d);
                fZ  += e * qZ;
                fS1 += e * (qS + d * qZ);
            }
        }
    }
    __syncthreads();
    if (tid < 128) { smx[tid] = fmx; sarg[tid] = farg; sZ[tid] = fZ; sS1[tid] = fS1; }
    __syncthreads();
    for (int s = 64; s; s >>= 1) {
        if (tid < s) {
            float qm = smx[tid + s], qZ = sZ[tid + s], qS = sS1[tid + s];
            int   qa = sarg[tid + s];
            if (qm > smx[tid] || (qm == smx[tid] && qa < sarg[tid])) {
                float d = fmaxf(smx[tid] - qm, -87.f);
                float e = expf(d);
                float Zo = sZ[tid], S1o = sS1[tid];
                sZ[tid]  = qZ + e * Zo;
                sS1[tid] = qS + e * (S1o + d * Zo);
                smx[tid] = qm; sarg[tid] = qa;
            } else {
                float d = fmaxf(qm - smx[tid], -87.f);
                float e = expf(d);
                sZ[tid]  += e * qZ;
                sS1[tid] += e * (qS + d * qZ);
            }
        }
        __syncthreads();
    }
    if (tid == 0) {
        float Zf = sZ[0], S1f = sS1[0];
        float logZ = logf(Zf);
        out[0] = (float)sarg[0];
        out[1] = 1.0f / Zf;          // p[idx]  (t=0 at argmax)
        out[2] = -logZ;              // logp[idx]
        out[3] = logZ - S1f / Zf;    // entropy
    }
}

// ---------------- launch ----------------
extern "C" void kernel_launch(void* const* d_in, const int* in_sizes, int n_in,
                              void* d_out, int out_size) {
    const float* x_graph = (const float*)d_in[0];
    const float* x_m     = (const float*)d_in[1];
    const float* x_job   = (const float*)d_in[2];
    const int*   m_ids   = (const int*)  d_in[3];
    const int*   job_idx = (const int*)  d_in[4];
    const float* W0      = (const float*)d_in[5];
    const float* b0      = (const float*)d_in[6];
    const float* W1      = (const float*)d_in[7];
    const float* b1      = (const float*)d_in[8];
    const float* W2      = (const float*)d_in[9];
    const float* b2      = (const float*)d_in[10];
    float* out = (float*)d_out;

    cudaFuncSetAttribute(score_kernel,
                         cudaFuncAttributeMaxDynamicSharedMemorySize, SMEM_SZ);

    score_kernel<<<SBLOCKS, 512, SMEM_SZ>>>(x_graph, x_m, x_job, W0, b0,
                                            m_ids, job_idx, W1, b1, W2, b2, out);
}